// round 13
// baseline (speedup 1.0000x reference)
#include <cuda_runtime.h>
#include <cuda_fp16.h>
#include <cstdint>
#include <math.h>

#define D_MODEL 1024
#define D_VOCAB 32000
#define NB 4
#define SEQ 1024
#define BT (NB * SEQ)
#define NLAYERS 6
#define BTV ((long)BT * D_VOCAB)
#define D2 (2 * D_MODEL)

// ---------------- scratch (device globals) ----------------------------------
__device__ float g_z [BT * D_MODEL];
__device__ float g_o [BT * D_MODEL];
__device__ float g_s [NB * SEQ * SEQ];
__device__ float g_nll[BT];

__device__ __half g_ylnf[BT * D_MODEL];
__device__ __half g_qkf [BT * D2];
__device__ __half g_sf  [NB * SEQ * SEQ];
__device__ __half g_vTf [BT * D_MODEL];
__device__ __half g_hf  [BT * D_MODEL];
__device__ __half g_zf  [BT * D_MODEL];
__device__ __half g_encf[(long)D_VOCAB * D_MODEL];
__device__ __half g_wtf [5 * D_MODEL * D_MODEL];   // wqT wkT wvT w1T w2T

// ---------------- helpers ----------------------------------------------------
__device__ __forceinline__ uint32_t smem_u32(const void* p) {
    uint32_t a;
    asm("{ .reg .u64 t; cvta.to.shared.u64 t, %1; cvt.u32.u64 %0, t; }" : "=r"(a) : "l"(p));
    return a;
}
__device__ __forceinline__ void ldsm4(uint32_t addr, uint32_t& r0, uint32_t& r1,
                                      uint32_t& r2, uint32_t& r3) {
    asm volatile("ldmatrix.sync.aligned.m8n8.x4.shared.b16 {%0,%1,%2,%3}, [%4];"
                 : "=r"(r0), "=r"(r1), "=r"(r2), "=r"(r3) : "r"(addr));
}
__device__ __forceinline__ void mma_fp16(float* c, uint32_t a0, uint32_t a1,
                                         uint32_t a2, uint32_t a3,
                                         uint32_t b0, uint32_t b1) {
    asm volatile(
        "mma.sync.aligned.m16n8k16.row.col.f32.f16.f16.f32 "
        "{%0,%1,%2,%3}, {%4,%5,%6,%7}, {%8,%9}, {%0,%1,%2,%3};"
        : "+f"(c[0]), "+f"(c[1]), "+f"(c[2]), "+f"(c[3])
        : "r"(a0), "r"(a1), "r"(a2), "r"(a3), "r"(b0), "r"(b1));
}
#define CP16(dst, src) \
    asm volatile("cp.async.cg.shared.global [%0], [%1], 16;" :: "r"(dst), "l"(src))
#define CP_COMMIT() asm volatile("cp.async.commit_group;" ::: "memory")
#define CP_WAIT1()  asm volatile("cp.async.wait_group 1;" ::: "memory")

// warp reduce; op 0 = sum, 1 = max
template <int OP>
__device__ __forceinline__ float warp_red(float v) {
    #pragma unroll
    for (int o = 16; o; o >>= 1) {
        float t = __shfl_xor_sync(0xffffffffu, v, o);
        v = OP ? fmaxf(v, t) : v + t;
    }
    return v;
}

// ---------------- fp16 single-pass GEMM NT, K-tile = 64 -----------------------
// C[m,n] = alpha * sum_k A[m,k]*B[n,k] (fp16 in, fp32 acc)
// flags: 1=relu 2=accum-C-fp32 4=bias 8=fp16-out(Cf) 16=fp32-out(C)
// grid (M/128, N/128, batch), 256 threads. K%64==0.
// smem rows are 128B (64 halves) with XOR-8 16B-chunk swizzle.
#define H_STAGE 32768           // 16KB A + 16KB B
#define NSTAGE 3
__global__ __launch_bounds__(256, 2) void gemm_h(
    const __half* __restrict__ A, const __half* __restrict__ B,
    const float* __restrict__ bias, float* __restrict__ C,
    __half* __restrict__ Cf,
    int lda, int ldb, int ldc, long sA, long sB, long sC,
    int K, float alpha, int flags) {

    extern __shared__ __align__(16) uint8_t sm[];

    A += (long)blockIdx.z * sA;
    B += (long)blockIdx.z * sB;
    if (C)  C  += (long)blockIdx.z * sC;
    if (Cf) Cf += (long)blockIdx.z * sC;

    const int tid  = threadIdx.x;
    const int wid  = tid >> 5;
    const int lane = tid & 31;
    const int warp_m = wid & 3;
    const int warp_n = wid >> 2;
    const int row0 = blockIdx.x * 128;
    const int col0 = blockIdx.y * 128;

    const uint32_t sbase = smem_u32(sm);

    const int lr = tid >> 1;           // 0..127: row
    const int lq = tid & 1;            // half of the 128B row
    const __half* Ap = A + (long)(row0 + lr) * lda;
    const __half* Bp = B + (long)(col0 + lr) * ldb;

    float acc[2][8][4];
    #pragma unroll
    for (int mb = 0; mb < 2; mb++)
        #pragma unroll
        for (int nb = 0; nb < 8; nb++)
            #pragma unroll
            for (int i = 0; i < 4; i++) acc[mb][nb][i] = 0.f;

    auto load_tile = [&](int kt, int st) {
        int k0 = kt << 6;
        uint32_t sb = sbase + st * H_STAGE;
        #pragma unroll
        for (int j = 0; j < 4; j++) {
            int c = lq * 4 + j;                       // 16B chunk 0..7
            uint32_t off = (uint32_t)(lr * 128 + ((c ^ (lr & 7)) * 16));
            CP16(sb + off,         Ap + k0 + c * 8);
            CP16(sb + 16384 + off, Bp + k0 + c * 8);
        }
    };

    const int KT = K >> 6;
    load_tile(0, 0); CP_COMMIT();
    if (KT > 1) { load_tile(1, 1); CP_COMMIT(); }
    else        { CP_COMMIT(); }

    for (int kt = 0; kt < KT; kt++) {
        CP_WAIT1();
        __syncthreads();
        if (kt + 2 < KT) load_tile(kt + 2, (kt + 2) % NSTAGE);
        CP_COMMIT();

        uint32_t sb = sbase + (kt % NSTAGE) * H_STAGE;
        #pragma unroll
        for (int kc = 0; kc < 4; kc++) {
            const int chunk = kc * 2 + (lane >> 4);   // 16B chunk 0..7
            uint32_t ah[2][4];
            #pragma unroll
            for (int mb = 0; mb < 2; mb++) {
                int mrow = warp_m * 32 + mb * 16 + (lane & 15);
                uint32_t off = (uint32_t)(mrow * 128 + ((chunk ^ (mrow & 7)) * 16));
                ldsm4(sb + off, ah[mb][0], ah[mb][1], ah[mb][2], ah[mb][3]);
            }
            #pragma unroll
            for (int nb4 = 0; nb4 < 4; nb4++) {
                int nrow = warp_n * 64 + nb4 * 16 + (lane & 15);
                uint32_t off = (uint32_t)(nrow * 128 + ((chunk ^ (nrow & 7)) * 16));
                uint32_t b0, b1, b2, b3;
                ldsm4(sb + 16384 + off, b0, b1, b2, b3);
                #pragma unroll
                for (int mb = 0; mb < 2; mb++) {
                    mma_fp16(acc[mb][nb4 * 2],     ah[mb][0], ah[mb][1], ah[mb][2], ah[mb][3], b0, b2);
                    mma_fp16(acc[mb][nb4 * 2 + 1], ah[mb][0], ah[mb][1], ah[mb][2], ah[mb][3], b1, b3);
                }
            }
        }
    }

    #pragma unroll
    for (int mb = 0; mb < 2; mb++) {
        #pragma unroll
        for (int nb = 0; nb < 8; nb++) {
            int m0 = row0 + warp_m * 32 + mb * 16 + (lane >> 2);
            int n0 = col0 + warp_n * 64 + nb * 8 + (lane & 3) * 2;
            #pragma unroll
            for (int half = 0; half < 2; half++) {
                int m = m0 + half * 8;
                float v0 = acc[mb][nb][half * 2 + 0] * alpha;
                float v1 = acc[mb][nb][half * 2 + 1] * alpha;
                if (flags & 4) { v0 += bias[n0]; v1 += bias[n0 + 1]; }
                if (flags & 1) { v0 = fmaxf(v0, 0.f); v1 = fmaxf(v1, 0.f); }
                long idx = (long)m * ldc + n0;
                if (flags & 2) { float2 o = *(float2*)(C + idx); v0 += o.x; v1 += o.y; }
                if (flags & 16) *(float2*)(C + idx) = make_float2(v0, v1);
                if (flags & 8)  *(__half2*)(Cf + idx) = __floats2half2_rn(v0, v1);
            }
        }
    }
}

// ---------------- transpose + fp32->fp16 -------------------------------------
__global__ void transpose_half(const float* __restrict__ src, __half* __restrict__ dst,
                               int R, int Ccols) {
    __shared__ float t[32][33];
    long ofs = (long)blockIdx.z * R * Ccols;
    src += ofs; dst += ofs;
    int bx = blockIdx.x * 32, by = blockIdx.y * 32;
    int x = bx + threadIdx.x;
    #pragma unroll
    for (int j = 0; j < 32; j += 8) {
        int y = by + threadIdx.y + j;
        t[threadIdx.y + j][threadIdx.x] = src[(long)y * Ccols + x];
    }
    __syncthreads();
    x = by + threadIdx.x;
    #pragma unroll
    for (int j = 0; j < 32; j += 8) {
        int y = bx + threadIdx.y + j;
        dst[(long)y * R + x] = __float2half_rn(t[threadIdx.x][threadIdx.y + j]);
    }
}

// ---------------- fp32 -> fp16 convert ---------------------------------------
__global__ void tohalf_kernel(const float* __restrict__ src, __half* __restrict__ dst,
                              long n4) {
    long i = (long)blockIdx.x * blockDim.x + threadIdx.x;
    long stride = (long)gridDim.x * blockDim.x;
    for (; i < n4; i += stride) {
        float4 v = ((const float4*)src)[i];
        ((__half2*)dst)[i * 2]     = __floats2half2_rn(v.x, v.y);
        ((__half2*)dst)[i * 2 + 1] = __floats2half2_rn(v.z, v.w);
    }
}

// ---------------- embedding gather ------------------------------------------
__global__ void embed_kernel(const int* __restrict__ x, const float* __restrict__ enc,
                             float* __restrict__ z) {
    int row = blockIdx.x;
    int tok = x[row];
    const float4* src = (const float4*)(enc + (long)tok * D_MODEL);
    float4* dst = (float4*)(z + (long)row * D_MODEL);
    for (int i = threadIdx.x; i < D_MODEL / 4; i += blockDim.x) dst[i] = src[i];
}

// ---------------- (buggy) LayerNorm, warp-per-row -> fp16 --------------------
__global__ __launch_bounds__(256) void ln_kernel(
    const float* __restrict__ in, const float* __restrict__ gamma,
    const float* __restrict__ beta, __half* __restrict__ outf) {
    int row  = blockIdx.x * 8 + (threadIdx.x >> 5);
    int lane = threadIdx.x & 31;
    const float4* xr = (const float4*)(in + (long)row * D_MODEL);

    float4 xv[8];
    float s = 0.f, s2 = 0.f;
    #pragma unroll
    for (int j = 0; j < 8; j++) {
        xv[j] = xr[lane + 32 * j];
        s  += xv[j].x + xv[j].y + xv[j].z + xv[j].w;
        s2 += xv[j].x * xv[j].x + xv[j].y * xv[j].y
            + xv[j].z * xv[j].z + xv[j].w * xv[j].w;
    }
    float S  = warp_red<0>(s);
    float S2 = warp_red<0>(s2);
    float mu  = S * (1.f / (float)D_MODEL);
    float var = (S2 - (float)D_MODEL * mu * mu) * (1.f / (float)(D_MODEL - 1));
    float shift = mu * rsqrtf(var);

    #pragma unroll
    for (int j = 0; j < 8; j++) {
        float4 g = ((const float4*)gamma)[lane + 32 * j];
        float4 b = ((const float4*)beta)[lane + 32 * j];
        long base = (long)row * D_MODEL + (lane + 32 * j) * 4;
        *(__half2*)(outf + base)     = __floats2half2_rn((xv[j].x - shift) * g.x + b.x,
                                                         (xv[j].y - shift) * g.y + b.y);
        *(__half2*)(outf + base + 2) = __floats2half2_rn((xv[j].z - shift) * g.z + b.z,
                                                         (xv[j].w - shift) * g.w + b.w);
    }
}

// ---------------- softmax, warp-per-row -> fp16 ------------------------------
__global__ __launch_bounds__(256) void softmax_kernel(
    const float* __restrict__ s, __half* __restrict__ outf) {
    int row  = blockIdx.x * 8 + (threadIdx.x >> 5);
    int lane = threadIdx.x & 31;
    const float4* r4 = (const float4*)(s + (long)row * SEQ);

    float4 v[8];
    float m = -1e30f;
    #pragma unroll
    for (int j = 0; j < 8; j++) {
        v[j] = r4[lane + 32 * j];
        m = fmaxf(m, fmaxf(fmaxf(v[j].x, v[j].y), fmaxf(v[j].z, v[j].w)));
    }
    float mx = warp_red<1>(m);

    float e[8][4];
    float sum = 0.f;
    #pragma unroll
    for (int j = 0; j < 8; j++) {
        e[j][0] = expf(v[j].x - mx); e[j][1] = expf(v[j].y - mx);
        e[j][2] = expf(v[j].z - mx); e[j][3] = expf(v[j].w - mx);
        sum += e[j][0] + e[j][1] + e[j][2] + e[j][3];
    }
    float inv = 1.f / warp_red<0>(sum);

    #pragma unroll
    for (int j = 0; j < 8; j++) {
        long base = (long)row * SEQ + (lane + 32 * j) * 4;
        *(__half2*)(outf + base)     = __floats2half2_rn(e[j][0] * inv, e[j][1] * inv);
        *(__half2*)(outf + base + 2) = __floats2half2_rn(e[j][2] * inv, e[j][3] * inv);
    }
}

// ---------------- per-row NLL: single-pass online logsumexp ------------------
__global__ void nll_kernel(const float* __restrict__ logits, const int* __restrict__ y,
                           float* __restrict__ nll) {
    int row = blockIdx.x;
    const float4* r4 = (const float4*)(logits + (long)row * D_VOCAB);
    int tid = threadIdx.x;
    const int NV4 = D_VOCAB / 4;

    float m = -1e30f, s = 0.f;
    for (int i = tid; i < NV4; i += 256) {
        float4 v = r4[i];
        float lm = fmaxf(fmaxf(v.x, v.y), fmaxf(v.z, v.w));
        if (lm > m) { s *= expf(m - lm); m = lm; }
        s += expf(v.x - m) + expf(v.y - m) + expf(v.z - m) + expf(v.w - m);
    }

    int lane = tid & 31, wid = tid >> 5;
    #pragma unroll
    for (int o = 16; o; o >>= 1) {
        float m2 = __shfl_xor_sync(0xffffffffu, m, o);
        float s2 = __shfl_xor_sync(0xffffffffu, s, o);
        float M = fmaxf(m, m2);
        s = s * expf(m - M) + s2 * expf(m2 - M);
        m = M;
    }
    __shared__ float sm_[8], ss_[8];
    if (lane == 0) { sm_[wid] = m; ss_[wid] = s; }
    __syncthreads();
    if (tid == 0) {
        float M = sm_[0];
        #pragma unroll
        for (int i = 1; i < 8; i++) M = fmaxf(M, sm_[i]);
        float S = 0.f;
        #pragma unroll
        for (int i = 0; i < 8; i++) S += ss_[i] * expf(sm_[i] - M);
        nll[row] = (M + logf(S)) - logits[(long)row * D_VOCAB + y[row]];
    }
}

__global__ void loss_reduce_kernel(const float* __restrict__ nll, float* __restrict__ out,
                                   long ofs) {
    __shared__ float red[256];
    int tid = threadIdx.x;
    float s = 0.f;
    for (int i = tid; i < BT; i += 256) s += nll[i];
    red[tid] = s; __syncthreads();
    #pragma unroll
    for (int o = 128; o > 0; o >>= 1) { if (tid < o) red[tid] += red[tid + o]; __syncthreads(); }
    if (tid == 0) out[ofs] = red[0] / (float)BT;
}

// ---------------- driver -----------------------------------------------------
extern "C" void kernel_launch(void* const* d_in, const int* in_sizes, int n_in,
                              void* d_out, int out_size) {
    (void)in_sizes; (void)n_in;
    const int*   x   = (const int*)  d_in[0];
    const int*   y   = (const int*)  d_in[1];
    const float* enc = (const float*)d_in[2];
    const float* g1  = (const float*)d_in[3];
    const float* b1  = (const float*)d_in[4];
    const float* wq  = (const float*)d_in[5];
    const float* wk  = (const float*)d_in[6];
    const float* wv  = (const float*)d_in[7];
    const float* g2  = (const float*)d_in[8];
    const float* b2  = (const float*)d_in[9];
    const float* w1  = (const float*)d_in[10];
    const float* bb1 = (const float*)d_in[11];
    const float* w2  = (const float*)d_in[12];
    const float* bb2 = (const float*)d_in[13];
    float* out = (float*)d_out;

    float *z, *o, *s, *nll;
    __half *ylnf, *qkf, *sf, *vTf, *hf, *zf, *encf, *wtf;
    cudaGetSymbolAddress((void**)&z,   g_z);
    cudaGetSymbolAddress((void**)&o,   g_o);
    cudaGetSymbolAddress((void**)&s,   g_s);
    cudaGetSymbolAddress((void**)&nll, g_nll);
    cudaGetSymbolAddress((void**)&ylnf, g_ylnf);
    cudaGetSymbolAddress((void**)&qkf, g_qkf);
    cudaGetSymbolAddress((void**)&sf, g_sf);
    cudaGetSymbolAddress((void**)&vTf, g_vTf);
    cudaGetSymbolAddress((void**)&hf, g_hf);
    cudaGetSymbolAddress((void**)&zf, g_zf);
    cudaGetSymbolAddress((void**)&encf, g_encf);
    cudaGetSymbolAddress((void**)&wtf, g_wtf);

    static int smem_set = 0;
    if (!smem_set) {
        cudaFuncSetAttribute(gemm_h, cudaFuncAttributeMaxDynamicSharedMemorySize,
                             NSTAGE * H_STAGE);
        smem_set = 1;
    }
    const int GH = NSTAGE * H_STAGE;

    const long DD = (long)D_MODEL * D_MODEL;
    const long SD = (long)SEQ * D_MODEL;
    const long SS = (long)SEQ * SEQ;
    const long S2 = (long)SEQ * D2;
    __half* wvTf = wtf + 2 * DD;
    __half* w1Tf = wtf + 3 * DD;
    __half* w2Tf = wtf + 4 * DD;

    dim3 tgrid(D_MODEL / 32, D_MODEL / 32, 1);
    dim3 tblk(32, 8);

    embed_kernel<<<BT, 256>>>(x, enc, z);
    transpose_half<<<tgrid, tblk>>>(wq, wtf + 0 * DD, D_MODEL, D_MODEL);
    transpose_half<<<tgrid, tblk>>>(wk, wtf + 1 * DD, D_MODEL, D_MODEL);
    transpose_half<<<tgrid, tblk>>>(wv, wvTf, D_MODEL, D_MODEL);
    transpose_half<<<tgrid, tblk>>>(w1, w1Tf, D_MODEL, D_MODEL);
    transpose_half<<<tgrid, tblk>>>(w2, w2Tf, D_MODEL, D_MODEL);
    tohalf_kernel<<<1024, 256>>>(enc, encf, (long)D_VOCAB * D_MODEL / 4);

    dim3 grid_qk  (BT / 128, D2 / 128);            // (32, 16)
    dim3 grid_proj(BT / 128, D_MODEL / 128);       // (32, 8)
    dim3 grid_attn(SEQ / 128, SEQ / 128, NB);      // (8, 8, 4)
    dim3 grid_vT  (D_MODEL / 128, SEQ / 128, NB);  // (8, 8, 4)

    for (int layer = 0; layer < NLAYERS; layer++) {
        ln_kernel<<<BT / 8, 256>>>(z, g1, b1, ylnf);

        // fused QK: [BT x 2048] = yln @ [wqT; wkT]^T -> fp16
        gemm_h<<<grid_qk, 256, GH>>>(ylnf, wtf, nullptr, nullptr, qkf,
                                     D_MODEL, D_MODEL, D2, 0, 0, 0, D_MODEL, 1.f, 8);

        // vT[d, t] = sum_k wvT[d,k] * yln[t,k]  -> fp16, per-batch
        gemm_h<<<grid_vT, 256, GH>>>(wvTf, ylnf, nullptr, nullptr, vTf,
                                     D_MODEL, D_MODEL, SEQ, 0, SD, SD, D_MODEL, 1.f, 8);

        // S = (Q K^T)/32 -> fp32
        gemm_h<<<grid_attn, 256, GH>>>(qkf, qkf + D_MODEL, nullptr, s, nullptr,
                                       D2, D2, SEQ, S2, S2, SS, D_MODEL, 0.03125f, 16);

        softmax_kernel<<<NB * SEQ / 8, 256>>>(s, sf);

        // O = S V -> fp32
        gemm_h<<<grid_attn, 256, GH>>>(sf, vTf, nullptr, o, nullptr,
                                       SEQ, SEQ, D_MODEL, SS, SD, SD, SEQ, 1.f, 16);

        ln_kernel<<<BT / 8, 256>>>(o, g2, b2, ylnf);

        // H = relu(Y W1 + b1) -> fp16
        gemm_h<<<grid_proj, 256, GH>>>(ylnf, w1Tf, bb1, nullptr, hf,
                                       D_MODEL, D_MODEL, D_MODEL, 0, 0, 0, D_MODEL,
                                       1.f, 8 | 4 | 1);
        // Z += H W2 + b2 -> fp32 accumulate; last layer also emits zf (fp16)
        int w2flags = 16 | 4 | 2 | ((layer == NLAYERS - 1) ? 8 : 0);
        gemm_h<<<grid_proj, 256, GH>>>(hf, w2Tf, bb2, z,
                                       (layer == NLAYERS - 1) ? zf : nullptr,
                                       D_MODEL, D_MODEL, D_MODEL, 0, 0, 0, D_MODEL,
                                       1.f, w2flags);
    }

    // logits = Z enc^T -> fp32
    dim3 grid_logits(BT / 128, D_VOCAB / 128);     // (32, 250)
    gemm_h<<<grid_logits, 256, GH>>>(zf, encf, nullptr, out, nullptr,
                                     D_MODEL, D_MODEL, D_VOCAB, 0, 0, 0, D_MODEL, 1.f, 16);

    nll_kernel<<<BT, 256>>>(out, y, nll);
    if ((long)out_size > BTV)
        loss_reduce_kernel<<<1, 256>>>(nll, out, BTV);
}

// round 14
// speedup vs baseline: 1.1487x; 1.1487x over previous
#include <cuda_runtime.h>
#include <cuda_fp16.h>
#include <cstdint>
#include <math.h>

#define D_MODEL 1024
#define D_VOCAB 32000
#define NB 4
#define SEQ 1024
#define BT (NB * SEQ)
#define NLAYERS 6
#define BTV ((long)BT * D_VOCAB)
#define D2 (2 * D_MODEL)
#define LSE_NB (D_VOCAB / 128)     // 250 column blocks in the logits GEMM

// ---------------- scratch (device globals) ----------------------------------
__device__ float g_z [BT * D_MODEL];
__device__ float g_o [BT * D_MODEL];
__device__ float g_s [NB * SEQ * SEQ];
__device__ float g_nll[BT];
__device__ float2 g_lse[(long)BT * LSE_NB];   // per (row, colblock) partial (max, sumexp)

__device__ __half g_ylnf[BT * D_MODEL];
__device__ __half g_qkf [BT * D2];
__device__ __half g_sf  [NB * SEQ * SEQ];
__device__ __half g_vTf [BT * D_MODEL];
__device__ __half g_hf  [BT * D_MODEL];
__device__ __half g_zf  [BT * D_MODEL];
__device__ __half g_encf[(long)D_VOCAB * D_MODEL];
__device__ __half g_wtf [5 * D_MODEL * D_MODEL];   // wqT wkT wvT w1T w2T

// ---------------- helpers ----------------------------------------------------
__device__ __forceinline__ uint32_t smem_u32(const void* p) {
    uint32_t a;
    asm("{ .reg .u64 t; cvta.to.shared.u64 t, %1; cvt.u32.u64 %0, t; }" : "=r"(a) : "l"(p));
    return a;
}
__device__ __forceinline__ void ldsm4(uint32_t addr, uint32_t& r0, uint32_t& r1,
                                      uint32_t& r2, uint32_t& r3) {
    asm volatile("ldmatrix.sync.aligned.m8n8.x4.shared.b16 {%0,%1,%2,%3}, [%4];"
                 : "=r"(r0), "=r"(r1), "=r"(r2), "=r"(r3) : "r"(addr));
}
__device__ __forceinline__ void mma_fp16(float* c, uint32_t a0, uint32_t a1,
                                         uint32_t a2, uint32_t a3,
                                         uint32_t b0, uint32_t b1) {
    asm volatile(
        "mma.sync.aligned.m16n8k16.row.col.f32.f16.f16.f32 "
        "{%0,%1,%2,%3}, {%4,%5,%6,%7}, {%8,%9}, {%0,%1,%2,%3};"
        : "+f"(c[0]), "+f"(c[1]), "+f"(c[2]), "+f"(c[3])
        : "r"(a0), "r"(a1), "r"(a2), "r"(a3), "r"(b0), "r"(b1));
}
#define CP16(dst, src) \
    asm volatile("cp.async.cg.shared.global [%0], [%1], 16;" :: "r"(dst), "l"(src))
#define CP_COMMIT() asm volatile("cp.async.commit_group;" ::: "memory")
#define CP_WAIT1()  asm volatile("cp.async.wait_group 1;" ::: "memory")

// warp reduce; op 0 = sum, 1 = max
template <int OP>
__device__ __forceinline__ float warp_red(float v) {
    #pragma unroll
    for (int o = 16; o; o >>= 1) {
        float t = __shfl_xor_sync(0xffffffffu, v, o);
        v = OP ? fmaxf(v, t) : v + t;
    }
    return v;
}

// ---------------- fp16 single-pass GEMM NT (R12 config, K-tile 32) -----------
// C[m,n] = alpha * sum_k A[m,k]*B[n,k] (fp16 in, fp32 acc)
// flags: 1=relu 2=accum-C-fp32 4=bias 8=fp16-out(Cf) 16=fp32-out(C)
//        32=emit per-(row, colblock) logsumexp partials into g_lse
// grid (M/128, N/128, batch), 256 threads. K%32==0.
#define H_STAGE 16384
#define NSTAGE 3
__global__ __launch_bounds__(256, 2) void gemm_h(
    const __half* __restrict__ A, const __half* __restrict__ B,
    const float* __restrict__ bias, float* __restrict__ C,
    __half* __restrict__ Cf,
    int lda, int ldb, int ldc, long sA, long sB, long sC,
    int K, float alpha, int flags) {

    extern __shared__ __align__(16) uint8_t sm[];

    A += (long)blockIdx.z * sA;
    B += (long)blockIdx.z * sB;
    if (C)  C  += (long)blockIdx.z * sC;
    if (Cf) Cf += (long)blockIdx.z * sC;

    const int tid  = threadIdx.x;
    const int wid  = tid >> 5;
    const int lane = tid & 31;
    const int warp_m = wid & 3;
    const int warp_n = wid >> 2;
    const int row0 = blockIdx.x * 128;
    const int col0 = blockIdx.y * 128;

    const uint32_t sbase = smem_u32(sm);

    const int lr = tid >> 1;
    const int lq = tid & 1;
    const int swz = (lr >> 1) & 3;
    const __half* Ap = A + (long)(row0 + lr) * lda;
    const __half* Bp = B + (long)(col0 + lr) * ldb;

    float acc[2][8][4];
    #pragma unroll
    for (int mb = 0; mb < 2; mb++)
        #pragma unroll
        for (int nb = 0; nb < 8; nb++)
            #pragma unroll
            for (int i = 0; i < 4; i++) acc[mb][nb][i] = 0.f;

    auto load_tile = [&](int kt, int st) {
        int k0 = kt << 5;
        uint32_t sb = sbase + st * H_STAGE;
        #pragma unroll
        for (int j = 0; j < 2; j++) {
            int c = lq * 2 + j;
            uint32_t off = (uint32_t)(lr * 64 + (c ^ swz) * 16);
            CP16(sb + off,        Ap + k0 + c * 8);
            CP16(sb + 8192 + off, Bp + k0 + c * 8);
        }
    };

    const int KT = K >> 5;
    load_tile(0, 0); CP_COMMIT();
    if (KT > 1) { load_tile(1, 1); CP_COMMIT(); }
    else        { CP_COMMIT(); }

    for (int kt = 0; kt < KT; kt++) {
        CP_WAIT1();
        __syncthreads();
        if (kt + 2 < KT) load_tile(kt + 2, (kt + 2) % NSTAGE);
        CP_COMMIT();

        uint32_t sb = sbase + (kt % NSTAGE) * H_STAGE;
        #pragma unroll
        for (int kc = 0; kc < 2; kc++) {
            const int chunkA = kc * 2 + (lane >> 4);
            uint32_t ah[2][4];
            #pragma unroll
            for (int mb = 0; mb < 2; mb++) {
                int mrow = warp_m * 32 + mb * 16 + (lane & 15);
                uint32_t off = (uint32_t)(mrow * 64 + (chunkA ^ ((mrow >> 1) & 3)) * 16);
                ldsm4(sb + off, ah[mb][0], ah[mb][1], ah[mb][2], ah[mb][3]);
            }
            #pragma unroll
            for (int nb4 = 0; nb4 < 4; nb4++) {
                int nrow = warp_n * 64 + nb4 * 16 + (lane & 15);
                uint32_t off = (uint32_t)(nrow * 64 + (chunkA ^ ((nrow >> 1) & 3)) * 16);
                uint32_t b0, b1, b2, b3;
                ldsm4(sb + 8192 + off, b0, b1, b2, b3);
                #pragma unroll
                for (int mb = 0; mb < 2; mb++) {
                    mma_fp16(acc[mb][nb4 * 2],     ah[mb][0], ah[mb][1], ah[mb][2], ah[mb][3], b0, b2);
                    mma_fp16(acc[mb][nb4 * 2 + 1], ah[mb][0], ah[mb][1], ah[mb][2], ah[mb][3], b1, b3);
                }
            }
        }
    }

    // ---- standard epilogue ----
    #pragma unroll
    for (int mb = 0; mb < 2; mb++) {
        #pragma unroll
        for (int nb = 0; nb < 8; nb++) {
            int m0 = row0 + warp_m * 32 + mb * 16 + (lane >> 2);
            int n0 = col0 + warp_n * 64 + nb * 8 + (lane & 3) * 2;
            #pragma unroll
            for (int half = 0; half < 2; half++) {
                int m = m0 + half * 8;
                float v0 = acc[mb][nb][half * 2 + 0] * alpha;
                float v1 = acc[mb][nb][half * 2 + 1] * alpha;
                if (flags & 4) { v0 += bias[n0]; v1 += bias[n0 + 1]; }
                if (flags & 1) { v0 = fmaxf(v0, 0.f); v1 = fmaxf(v1, 0.f); }
                long idx = (long)m * ldc + n0;
                if (flags & 2) { float2 o = *(float2*)(C + idx); v0 += o.x; v1 += o.y; }
                if (flags & 16) *(float2*)(C + idx) = make_float2(v0, v1);
                if (flags & 8)  *(__half2*)(Cf + idx) = __floats2half2_rn(v0, v1);
            }
        }
    }

    // ---- fused logsumexp partials (logits GEMM only; alpha == 1) ----
    if (flags & 32) {
        __shared__ float2 lse_sh[128];
        float msm[2][2], mss[2][2];
        #pragma unroll
        for (int mb = 0; mb < 2; mb++) {
            #pragma unroll
            for (int half = 0; half < 2; half++) {
                float lm = -1e30f;
                #pragma unroll
                for (int nb = 0; nb < 8; nb++)
                    lm = fmaxf(lm, fmaxf(acc[mb][nb][half * 2], acc[mb][nb][half * 2 + 1]));
                float ls = 0.f;
                #pragma unroll
                for (int nb = 0; nb < 8; nb++)
                    ls += expf(acc[mb][nb][half * 2] - lm) +
                          expf(acc[mb][nb][half * 2 + 1] - lm);
                // combine across the 4 lanes sharing this row (lane&3 = col id)
                #pragma unroll
                for (int o = 1; o <= 2; o <<= 1) {
                    float m2 = __shfl_xor_sync(0xffffffffu, lm, o);
                    float s2 = __shfl_xor_sync(0xffffffffu, ls, o);
                    float M = fmaxf(lm, m2);
                    ls = ls * expf(lm - M) + s2 * expf(m2 - M);
                    lm = M;
                }
                msm[mb][half] = lm; mss[mb][half] = ls;
                int lrow = warp_m * 32 + mb * 16 + half * 8 + (lane >> 2);
                if (warp_n == 1 && (lane & 3) == 0)
                    lse_sh[lrow] = make_float2(lm, ls);
            }
        }
        __syncthreads();
        if (warp_n == 0 && (lane & 3) == 0) {
            float2* lse = g_lse;
            #pragma unroll
            for (int mb = 0; mb < 2; mb++) {
                #pragma unroll
                for (int half = 0; half < 2; half++) {
                    int lrow = warp_m * 32 + mb * 16 + half * 8 + (lane >> 2);
                    float2 o = lse_sh[lrow];
                    float M = fmaxf(msm[mb][half], o.x);
                    float S = mss[mb][half] * expf(msm[mb][half] - M) +
                              o.y * expf(o.x - M);
                    lse[(long)(row0 + lrow) * gridDim.y + blockIdx.y] = make_float2(M, S);
                }
            }
        }
    }
}

// ---------------- transpose + fp32->fp16 -------------------------------------
__global__ void transpose_half(const float* __restrict__ src, __half* __restrict__ dst,
                               int R, int Ccols) {
    __shared__ float t[32][33];
    long ofs = (long)blockIdx.z * R * Ccols;
    src += ofs; dst += ofs;
    int bx = blockIdx.x * 32, by = blockIdx.y * 32;
    int x = bx + threadIdx.x;
    #pragma unroll
    for (int j = 0; j < 32; j += 8) {
        int y = by + threadIdx.y + j;
        t[threadIdx.y + j][threadIdx.x] = src[(long)y * Ccols + x];
    }
    __syncthreads();
    x = by + threadIdx.x;
    #pragma unroll
    for (int j = 0; j < 32; j += 8) {
        int y = bx + threadIdx.y + j;
        dst[(long)y * R + x] = __float2half_rn(t[threadIdx.x][threadIdx.y + j]);
    }
}

// ---------------- fp32 -> fp16 convert ---------------------------------------
__global__ void tohalf_kernel(const float* __restrict__ src, __half* __restrict__ dst,
                              long n4) {
    long i = (long)blockIdx.x * blockDim.x + threadIdx.x;
    long stride = (long)gridDim.x * blockDim.x;
    for (; i < n4; i += stride) {
        float4 v = ((const float4*)src)[i];
        ((__half2*)dst)[i * 2]     = __floats2half2_rn(v.x, v.y);
        ((__half2*)dst)[i * 2 + 1] = __floats2half2_rn(v.z, v.w);
    }
}

// ---------------- embedding gather ------------------------------------------
__global__ void embed_kernel(const int* __restrict__ x, const float* __restrict__ enc,
                             float* __restrict__ z) {
    int row = blockIdx.x;
    int tok = x[row];
    const float4* src = (const float4*)(enc + (long)tok * D_MODEL);
    float4* dst = (float4*)(z + (long)row * D_MODEL);
    for (int i = threadIdx.x; i < D_MODEL / 4; i += blockDim.x) dst[i] = src[i];
}

// ---------------- (buggy) LayerNorm, warp-per-row -> fp16 --------------------
__global__ __launch_bounds__(256) void ln_kernel(
    const float* __restrict__ in, const float* __restrict__ gamma,
    const float* __restrict__ beta, __half* __restrict__ outf) {
    int row  = blockIdx.x * 8 + (threadIdx.x >> 5);
    int lane = threadIdx.x & 31;
    const float4* xr = (const float4*)(in + (long)row * D_MODEL);

    float4 xv[8];
    float s = 0.f, s2 = 0.f;
    #pragma unroll
    for (int j = 0; j < 8; j++) {
        xv[j] = xr[lane + 32 * j];
        s  += xv[j].x + xv[j].y + xv[j].z + xv[j].w;
        s2 += xv[j].x * xv[j].x + xv[j].y * xv[j].y
            + xv[j].z * xv[j].z + xv[j].w * xv[j].w;
    }
    float S  = warp_red<0>(s);
    float S2 = warp_red<0>(s2);
    float mu  = S * (1.f / (float)D_MODEL);
    float var = (S2 - (float)D_MODEL * mu * mu) * (1.f / (float)(D_MODEL - 1));
    float shift = mu * rsqrtf(var);

    #pragma unroll
    for (int j = 0; j < 8; j++) {
        float4 g = ((const float4*)gamma)[lane + 32 * j];
        float4 b = ((const float4*)beta)[lane + 32 * j];
        long base = (long)row * D_MODEL + (lane + 32 * j) * 4;
        *(__half2*)(outf + base)     = __floats2half2_rn((xv[j].x - shift) * g.x + b.x,
                                                         (xv[j].y - shift) * g.y + b.y);
        *(__half2*)(outf + base + 2) = __floats2half2_rn((xv[j].z - shift) * g.z + b.z,
                                                         (xv[j].w - shift) * g.w + b.w);
    }
}

// ---------------- softmax, warp-per-row -> fp16 ------------------------------
__global__ __launch_bounds__(256) void softmax_kernel(
    const float* __restrict__ s, __half* __restrict__ outf) {
    int row  = blockIdx.x * 8 + (threadIdx.x >> 5);
    int lane = threadIdx.x & 31;
    const float4* r4 = (const float4*)(s + (long)row * SEQ);

    float4 v[8];
    float m = -1e30f;
    #pragma unroll
    for (int j = 0; j < 8; j++) {
        v[j] = r4[lane + 32 * j];
        m = fmaxf(m, fmaxf(fmaxf(v[j].x, v[j].y), fmaxf(v[j].z, v[j].w)));
    }
    float mx = warp_red<1>(m);

    float e[8][4];
    float sum = 0.f;
    #pragma unroll
    for (int j = 0; j < 8; j++) {
        e[j][0] = expf(v[j].x - mx); e[j][1] = expf(v[j].y - mx);
        e[j][2] = expf(v[j].z - mx); e[j][3] = expf(v[j].w - mx);
        sum += e[j][0] + e[j][1] + e[j][2] + e[j][3];
    }
    float inv = 1.f / warp_red<0>(sum);

    #pragma unroll
    for (int j = 0; j < 8; j++) {
        long base = (long)row * SEQ + (lane + 32 * j) * 4;
        *(__half2*)(outf + base)     = __floats2half2_rn(e[j][0] * inv, e[j][1] * inv);
        *(__half2*)(outf + base + 2) = __floats2half2_rn(e[j][2] * inv, e[j][3] * inv);
    }
}

// ---------------- final NLL from per-colblock LSE partials -------------------
__global__ void nll_final(const float2* __restrict__ lse,
                          const float* __restrict__ logits,
                          const int* __restrict__ y, float* __restrict__ nll) {
    int row = blockIdx.x;
    int tid = threadIdx.x;

    float m = -1e30f, s = 0.f;
    if (tid < LSE_NB) {
        float2 p = lse[(long)row * LSE_NB + tid];
        m = p.x; s = p.y;
    }

    int lane = tid & 31, wid = tid >> 5;
    #pragma unroll
    for (int o = 16; o; o >>= 1) {
        float m2 = __shfl_xor_sync(0xffffffffu, m, o);
        float s2 = __shfl_xor_sync(0xffffffffu, s, o);
        float M = fmaxf(m, m2);
        s = s * expf(m - M) + s2 * expf(m2 - M);
        m = M;
    }
    __shared__ float sm_[8], ss_[8];
    if (lane == 0) { sm_[wid] = m; ss_[wid] = s; }
    __syncthreads();
    if (tid == 0) {
        float M = sm_[0];
        #pragma unroll
        for (int i = 1; i < 8; i++) M = fmaxf(M, sm_[i]);
        float S = 0.f;
        #pragma unroll
        for (int i = 0; i < 8; i++) S += ss_[i] * expf(sm_[i] - M);
        nll[row] = (M + logf(S)) - logits[(long)row * D_VOCAB + y[row]];
    }
}

__global__ void loss_reduce_kernel(const float* __restrict__ nll, float* __restrict__ out,
                                   long ofs) {
    __shared__ float red[256];
    int tid = threadIdx.x;
    float s = 0.f;
    for (int i = tid; i < BT; i += 256) s += nll[i];
    red[tid] = s; __syncthreads();
    #pragma unroll
    for (int o = 128; o > 0; o >>= 1) { if (tid < o) red[tid] += red[tid + o]; __syncthreads(); }
    if (tid == 0) out[ofs] = red[0] / (float)BT;
}

// ---------------- driver -----------------------------------------------------
extern "C" void kernel_launch(void* const* d_in, const int* in_sizes, int n_in,
                              void* d_out, int out_size) {
    (void)in_sizes; (void)n_in;
    const int*   x   = (const int*)  d_in[0];
    const int*   y   = (const int*)  d_in[1];
    const float* enc = (const float*)d_in[2];
    const float* g1  = (const float*)d_in[3];
    const float* b1  = (const float*)d_in[4];
    const float* wq  = (const float*)d_in[5];
    const float* wk  = (const float*)d_in[6];
    const float* wv  = (const float*)d_in[7];
    const float* g2  = (const float*)d_in[8];
    const float* b2  = (const float*)d_in[9];
    const float* w1  = (const float*)d_in[10];
    const float* bb1 = (const float*)d_in[11];
    const float* w2  = (const float*)d_in[12];
    const float* bb2 = (const float*)d_in[13];
    float* out = (float*)d_out;

    float *z, *o, *s, *nll;
    float2* lse;
    __half *ylnf, *qkf, *sf, *vTf, *hf, *zf, *encf, *wtf;
    cudaGetSymbolAddress((void**)&z,   g_z);
    cudaGetSymbolAddress((void**)&o,   g_o);
    cudaGetSymbolAddress((void**)&s,   g_s);
    cudaGetSymbolAddress((void**)&nll, g_nll);
    cudaGetSymbolAddress((void**)&lse, g_lse);
    cudaGetSymbolAddress((void**)&ylnf, g_ylnf);
    cudaGetSymbolAddress((void**)&qkf, g_qkf);
    cudaGetSymbolAddress((void**)&sf, g_sf);
    cudaGetSymbolAddress((void**)&vTf, g_vTf);
    cudaGetSymbolAddress((void**)&hf, g_hf);
    cudaGetSymbolAddress((void**)&zf, g_zf);
    cudaGetSymbolAddress((void**)&encf, g_encf);
    cudaGetSymbolAddress((void**)&wtf, g_wtf);

    static int smem_set = 0;
    if (!smem_set) {
        cudaFuncSetAttribute(gemm_h, cudaFuncAttributeMaxDynamicSharedMemorySize,
                             NSTAGE * H_STAGE);
        smem_set = 1;
    }
    const int GH = NSTAGE * H_STAGE;

    const long DD = (long)D_MODEL * D_MODEL;
    const long SD = (long)SEQ * D_MODEL;
    const long SS = (long)SEQ * SEQ;
    const long S2 = (long)SEQ * D2;
    __half* wvTf = wtf + 2 * DD;
    __half* w1Tf = wtf + 3 * DD;
    __half* w2Tf = wtf + 4 * DD;

    dim3 tgrid(D_MODEL / 32, D_MODEL / 32, 1);
    dim3 tblk(32, 8);

    embed_kernel<<<BT, 256>>>(x, enc, z);
    transpose_half<<<tgrid, tblk>>>(wq, wtf + 0 * DD, D_MODEL, D_MODEL);
    transpose_half<<<tgrid, tblk>>>(wk, wtf + 1 * DD, D_MODEL, D_MODEL);
    transpose_half<<<tgrid, tblk>>>(wv, wvTf, D_MODEL, D_MODEL);
    transpose_half<<<tgrid, tblk>>>(w1, w1Tf, D_MODEL, D_MODEL);
    transpose_half<<<tgrid, tblk>>>(w2, w2Tf, D_MODEL, D_MODEL);
    tohalf_kernel<<<1024, 256>>>(enc, encf, (long)D_VOCAB * D_MODEL / 4);

    dim3 grid_qk  (BT / 128, D2 / 128);            // (32, 16)
    dim3 grid_proj(BT / 128, D_MODEL / 128);       // (32, 8)
    dim3 grid_attn(SEQ / 128, SEQ / 128, NB);      // (8, 8, 4)
    dim3 grid_vT  (D_MODEL / 128, SEQ / 128, NB);  // (8, 8, 4)

    for (int layer = 0; layer < NLAYERS; layer++) {
        ln_kernel<<<BT / 8, 256>>>(z, g1, b1, ylnf);

        // fused QK: [BT x 2048] = yln @ [wqT; wkT]^T -> fp16
        gemm_h<<<grid_qk, 256, GH>>>(ylnf, wtf, nullptr, nullptr, qkf,
                                     D_MODEL, D_MODEL, D2, 0, 0, 0, D_MODEL, 1.f, 8);

        // vT[d, t] = sum_k wvT[d,k] * yln[t,k]  -> fp16, per-batch
        gemm_h<<<grid_vT, 256, GH>>>(wvTf, ylnf, nullptr, nullptr, vTf,
                                     D_MODEL, D_MODEL, SEQ, 0, SD, SD, D_MODEL, 1.f, 8);

        // S = (Q K^T)/32 -> fp32
        gemm_h<<<grid_attn, 256, GH>>>(qkf, qkf + D_MODEL, nullptr, s, nullptr,
                                       D2, D2, SEQ, S2, S2, SS, D_MODEL, 0.03125f, 16);

        softmax_kernel<<<NB * SEQ / 8, 256>>>(s, sf);

        // O = S V -> fp32
        gemm_h<<<grid_attn, 256, GH>>>(sf, vTf, nullptr, o, nullptr,
                                       SEQ, SEQ, D_MODEL, SS, SD, SD, SEQ, 1.f, 16);

        ln_kernel<<<BT / 8, 256>>>(o, g2, b2, ylnf);

        // H = relu(Y W1 + b1) -> fp16
        gemm_h<<<grid_proj, 256, GH>>>(ylnf, w1Tf, bb1, nullptr, hf,
                                       D_MODEL, D_MODEL, D_MODEL, 0, 0, 0, D_MODEL,
                                       1.f, 8 | 4 | 1);
        // Z += H W2 + b2 -> fp32 accumulate; last layer also emits zf (fp16)
        int w2flags = 16 | 4 | 2 | ((layer == NLAYERS - 1) ? 8 : 0);
        gemm_h<<<grid_proj, 256, GH>>>(hf, w2Tf, bb2, z,
                                       (layer == NLAYERS - 1) ? zf : nullptr,
                                       D_MODEL, D_MODEL, D_MODEL, 0, 0, 0, D_MODEL,
                                       1.f, w2flags);
    }

    // logits = Z enc^T -> fp32, with fused per-colblock logsumexp partials
    dim3 grid_logits(BT / 128, D_VOCAB / 128);     // (32, 250)
    gemm_h<<<grid_logits, 256, GH>>>(zf, encf, nullptr, out, nullptr,
                                     D_MODEL, D_MODEL, D_VOCAB, 0, 0, 0, D_MODEL,
                                     1.f, 16 | 32);

    nll_final<<<BT, 256>>>(lse, out, y, nll);
    if ((long)out_size > BTV)
        loss_reduce_kernel<<<1, 256>>>(nll, out, BTV);
}